// round 17
// baseline (speedup 1.0000x reference)
#include <cuda_runtime.h>

// DihedralToCartesian R17: ILP=2 per lane. Each warp owns 4 chains: lanes
// 0-15 run segment s of chains A,B as two interleaved register streams,
// lanes 16-31 chains C,D. Total instructions unchanged, warps halved, every
// phase-1/scan stall slot gets a second independent stream.
// Scan slimmed to 9 carried values (c1, c3, p); c2/L2 recomputed as g3 x g1
// (valid: maps stay orthonormal right-handed). Chain math identical to R16.

#define TPB    128
#define NWARP  4
#define NRES   126
#define LSEG   9
#define SEGN   14
#define RECF   1008            // record floats per warp (4 chains * 126 * 2)
#define OUTF   1512            // output floats per warp (4 * 378)

__device__ __forceinline__ float frsqrt(float x) {
    float y;
    asm("rsqrt.approx.f32 %0, %1;" : "=f"(y) : "f"(x));
    return y;
}

struct St { float px, py, pz, wx, wy, wz, nx, ny, nz; };

__device__ __forceinline__ void step_fn(St& S, float2 cs,
                                        float CAk, float Bk, float SAk,
                                        float& qx, float& qy, float& qz)
{
    float a = SAk * cs.x, b = SAk * cs.y;
    float mx = S.wy * S.nz - S.wz * S.ny;
    float my = S.wz * S.nx - S.wx * S.nz;
    float mz = S.wx * S.ny - S.wy * S.nx;
    float ux = fmaf(-CAk, S.wx, fmaf(a, mx, -b * S.nx));
    float uy = fmaf(-CAk, S.wy, fmaf(a, my, -b * S.ny));
    float uz = fmaf(-CAk, S.wz, fmaf(a, mz, -b * S.nz));
    S.px = fmaf(Bk, ux, S.px);
    S.py = fmaf(Bk, uy, S.py);
    S.pz = fmaf(Bk, uz, S.pz);
    qx = S.px; qy = S.py; qz = S.pz;
    float n2x = fmaf(cs.x, S.nx, cs.y * mx);
    float n2y = fmaf(cs.x, S.ny, cs.y * my);
    float n2z = fmaf(cs.x, S.nz, cs.y * mz);
    S.nx = n2x; S.ny = n2y; S.nz = n2z;
    S.wx = ux;  S.wy = uy;  S.wz = uz;
}

// reference-faithful first step on raw prev_three geometry
__device__ __forceinline__ void peel_fn(St& S, const float* pp, float2 cs0,
                                        float& qx, float& qy, float& qz)
{
    const float CA0 = cosf(2.028f), SA0 = sinf(2.028f), B0 = 1.329f;
    float ax = pp[0], ay = pp[1], az = pp[2];
    float bx = pp[3], by = pp[4], bz = pp[5];
    S.px = pp[6]; S.py = pp[7]; S.pz = pp[8];

    float cn = cs0.x, sm = cs0.y;
    float r1 = SA0 * cn, r2 = -SA0 * sm;

    float bcx = (bx - S.px) + 1e-8f;
    float bcy = (by - S.py) + 1e-8f;
    float bcz = (bz - S.pz) + 1e-8f;
    float ib = frsqrt(fmaf(bcx, bcx, fmaf(bcy, bcy, bcz * bcz)));
    bcx *= ib; bcy *= ib; bcz *= ib;

    float vqx = bx - ax, vqy = by - ay, vqz = bz - az;
    float Nx = fmaf(vqy, bcz, fmaf(-vqz, bcy, 1e-8f));
    float Ny = fmaf(vqz, bcx, fmaf(-vqx, bcz, 1e-8f));
    float Nz = fmaf(vqx, bcy, fmaf(-vqy, bcx, 1e-8f));
    float iN = frsqrt(fmaf(Nx, Nx, fmaf(Ny, Ny, Nz * Nz)));
    Nx *= iN; Ny *= iN; Nz *= iN;

    float mx = Ny * bcz - Nz * bcy;
    float my = Nz * bcx - Nx * bcz;
    float mz = Nx * bcy - Ny * bcx;

    float ux = fmaf(CA0, bcx, fmaf(r1, mx, r2 * Nx));
    float uy = fmaf(CA0, bcy, fmaf(r1, my, r2 * Ny));
    float uz = fmaf(CA0, bcz, fmaf(r1, mz, r2 * Nz));

    S.px = fmaf(B0, ux, S.px);
    S.py = fmaf(B0, uy, S.py);
    S.pz = fmaf(B0, uz, S.pz);
    qx = S.px; qy = S.py; qz = S.pz;

    S.wx = ux; S.wy = uy; S.wz = uz;            // |u| = 1 + O(eps)
    S.nx = fmaf(cn, Nx, sm * mx);               // n' = cn*N + sm*m
    S.ny = fmaf(cn, Ny, sm * my);
    S.nz = fmaf(cn, Nz, sm * mz);
}

__device__ __forceinline__ void fix_fn(St& S)   // renorm w; reortho+renorm n
{
    float iw = frsqrt(fmaf(S.wx, S.wx, fmaf(S.wy, S.wy, S.wz * S.wz)));
    S.wx *= iw; S.wy *= iw; S.wz *= iw;
    float d = fmaf(S.nx, S.wx, fmaf(S.ny, S.wy, S.nz * S.wz));
    S.nx = fmaf(-d, S.wx, S.nx);
    S.ny = fmaf(-d, S.wy, S.ny);
    S.nz = fmaf(-d, S.wz, S.nz);
    float in_ = frsqrt(fmaf(S.nx, S.nx, fmaf(S.ny, S.ny, S.nz * S.nz)));
    S.nx *= in_; S.ny *= in_; S.nz *= in_;
}

__global__ void __launch_bounds__(TPB, 5)
dihedral_kernel(const float* __restrict__ angles,
                const float* __restrict__ prev,
                float* __restrict__ out)
{
    __shared__ __align__(16) float stg[NWARP][RECF + OUTF];

    const int lane = threadIdx.x & 31;
    const int wl   = threadIdx.x >> 5;
    const int grp  = lane >> 4;          // 0: chains A,B   1: chains C,D
    const int s    = lane & 15;          // segment id
    const bool act = (s < SEGN);

    const int chain0 = blockIdx.x * (NWARP * 4) + wl * 4;   // 4 chains/warp

    const float CA0 = cosf(2.028f), SA0 = sinf(2.028f), B0 = 1.329f;
    const float CA1 = cosf(2.124f), SA1 = sinf(2.124f), B1 = 1.458f;
    const float CA2 = cosf(1.941f), SA2 = sinf(1.941f), B2 = 1.523f;

    float* sw = stg[wl];

    // ---- phase 0: load sin/cos for 4 chains, normalize, store (cn,sm) ----
    {
        const float* gA = angles + (size_t)chain0 * (2 * NRES);
        float4* rec4 = (float4*)sw;
        #pragma unroll
        for (int i = 0; i < 8; ++i) {
            int pr = 2 * lane + 64 * i;              // even global pair index
            if (pr < 4 * NRES) {
                int cc = pr / NRES;
                int j  = pr - cc * NRES;
                const float* row = gA + cc * (2 * NRES);
                float2 s2 = *(const float2*)(row + j);
                float2 c2 = *(const float2*)(row + NRES + j);
                float i0 = frsqrt(fmaf(s2.x, s2.x, fmaf(c2.x, c2.x, 1e-8f)));
                float i1 = frsqrt(fmaf(s2.y, s2.y, fmaf(c2.y, c2.y, 1e-8f)));
                rec4[pr >> 1] = make_float4(c2.x * i0, s2.x * i0,
                                            c2.y * i1, s2.y * i1);
            }
        }
    }
    __syncwarp();

    const int j0c = (s < SEGN ? s : SEGN - 1) * LSEG;
    const float2* rcpA = (const float2*)sw + (grp * 2 + 0) * NRES + j0c;
    const float2* rcpB = (const float2*)sw + (grp * 2 + 1) * NRES + j0c;

    // ---- phase 1: two interleaved 9-step chains per lane ----
    St A, B;
    float qA[LSEG * 3], qB[LSEG * 3];

    #define STEP2(jj, CAk, Bk, SAk)                                             \
        step_fn(A, rcpA[jj], CAk, Bk, SAk,                                      \
                qA[(jj)*3], qA[(jj)*3+1], qA[(jj)*3+2]);                        \
        step_fn(B, rcpB[jj], CAk, Bk, SAk,                                      \
                qB[(jj)*3], qB[(jj)*3+1], qB[(jj)*3+2]);

    if (s == 0) {
        const float* ppA = prev + (size_t)(chain0 + grp * 2 + 0) * 9;
        const float* ppB = prev + (size_t)(chain0 + grp * 2 + 1) * 9;
        peel_fn(A, ppA, rcpA[0], qA[0], qA[1], qA[2]);
        peel_fn(B, ppB, rcpB[0], qB[0], qB[1], qB[2]);
    } else {
        A.px = 0.f; A.py = 0.f; A.pz = 0.f;
        A.wx = 1.f; A.wy = 0.f; A.wz = 0.f;
        A.nx = 0.f; A.ny = 0.f; A.nz = 1.f;
        B = A;
        STEP2(0, CA0, B0, SA0)
    }
    STEP2(1, CA1, B1, SA1)
    STEP2(2, CA2, B2, SA2)
    STEP2(3, CA0, B0, SA0)
    STEP2(4, CA1, B1, SA1)
    fix_fn(A); fix_fn(B);
    STEP2(5, CA2, B2, SA2)
    STEP2(6, CA0, B0, SA0)
    STEP2(7, CA1, B1, SA1)
    STEP2(8, CA2, B2, SA2)
    #undef STEP2

    // ---- phase 2: exit basis (c1 = w, c3 = n_perp); c2 never materialized --
    float a1x, a1y, a1z, a3x, a3y, a3z, apx, apy, apz;
    float b1x, b1y, b1z, b3x, b3y, b3z, bpx, bpy, bpz;
    {
        float iw = frsqrt(fmaf(A.wx, A.wx, fmaf(A.wy, A.wy, A.wz * A.wz)));
        a1x = A.wx * iw; a1y = A.wy * iw; a1z = A.wz * iw;
        float d = fmaf(A.nx, a1x, fmaf(A.ny, a1y, A.nz * a1z));
        float tx = fmaf(-d, a1x, A.nx);
        float ty = fmaf(-d, a1y, A.ny);
        float tz = fmaf(-d, a1z, A.nz);
        float it = frsqrt(fmaf(tx, tx, fmaf(ty, ty, fmaf(tz, tz, 1e-20f))));
        a3x = tx * it; a3y = ty * it; a3z = tz * it;
        apx = A.px; apy = A.py; apz = A.pz;
    }
    {
        float iw = frsqrt(fmaf(B.wx, B.wx, fmaf(B.wy, B.wy, B.wz * B.wz)));
        b1x = B.wx * iw; b1y = B.wy * iw; b1z = B.wz * iw;
        float d = fmaf(B.nx, b1x, fmaf(B.ny, b1y, B.nz * b1z));
        float tx = fmaf(-d, b1x, B.nx);
        float ty = fmaf(-d, b1y, B.ny);
        float tz = fmaf(-d, b1z, B.nz);
        float it = frsqrt(fmaf(tx, tx, fmaf(ty, ty, fmaf(tz, tz, 1e-20f))));
        b3x = tx * it; b3y = ty * it; b3z = tz * it;
        bpx = B.px; bpy = B.py; bpz = B.pz;
    }

    // ---- Hillis-Steele scan over rigid maps, 9 carried values per set ----
    // compose with left map L: L2 = L3 x L1 (orthonormal RH), then
    // c1' = c1x*L1 + c1y*L2 + c1z*L3 ; c3' analogous ; p' = R_L*p + L.p
    #define SCAN_SET(c1x,c1y,c1z, c3x,c3y,c3z, cpx,cpy,cpz, d)                  \
    {                                                                           \
        float L1x = __shfl_up_sync(0xffffffffu, c1x, d, 16);                    \
        float L1y = __shfl_up_sync(0xffffffffu, c1y, d, 16);                    \
        float L1z = __shfl_up_sync(0xffffffffu, c1z, d, 16);                    \
        float L3x = __shfl_up_sync(0xffffffffu, c3x, d, 16);                    \
        float L3y = __shfl_up_sync(0xffffffffu, c3y, d, 16);                    \
        float L3z = __shfl_up_sync(0xffffffffu, c3z, d, 16);                    \
        float Lpx = __shfl_up_sync(0xffffffffu, cpx, d, 16);                    \
        float Lpy = __shfl_up_sync(0xffffffffu, cpy, d, 16);                    \
        float Lpz = __shfl_up_sync(0xffffffffu, cpz, d, 16);                    \
        float L2x = L3y * L1z - L3z * L1y;                                      \
        float L2y = L3z * L1x - L3x * L1z;                                      \
        float L2z = L3x * L1y - L3y * L1x;                                      \
        if (s >= d) {                                                           \
            float n1x = fmaf(c1x, L1x, fmaf(c1y, L2x, c1z * L3x));              \
            float n1y = fmaf(c1x, L1y, fmaf(c1y, L2y, c1z * L3y));              \
            float n1z = fmaf(c1x, L1z, fmaf(c1y, L2z, c1z * L3z));              \
            float n3x = fmaf(c3x, L1x, fmaf(c3y, L2x, c3z * L3x));              \
            float n3y = fmaf(c3x, L1y, fmaf(c3y, L2y, c3z * L3y));              \
            float n3z = fmaf(c3x, L1z, fmaf(c3y, L2z, c3z * L3z));              \
            float npx = fmaf(cpx, L1x, fmaf(cpy, L2x, fmaf(cpz, L3x, Lpx)));    \
            float npy = fmaf(cpx, L1y, fmaf(cpy, L2y, fmaf(cpz, L3y, Lpy)));    \
            float npz = fmaf(cpx, L1z, fmaf(cpy, L2z, fmaf(cpz, L3z, Lpz)));    \
            c1x = n1x; c1y = n1y; c1z = n1z;                                    \
            c3x = n3x; c3y = n3y; c3z = n3z;                                    \
            cpx = npx; cpy = npy; cpz = npz;                                    \
        }                                                                       \
    }

    #pragma unroll
    for (int d = 1; d < 16; d <<= 1) {
        SCAN_SET(a1x,a1y,a1z, a3x,a3y,a3z, apx,apy,apz, d)
        SCAN_SET(b1x,b1y,b1z, b3x,b3y,b3z, bpx,bpy,bpz, d)
    }
    #undef SCAN_SET

    // ---- exclusive prefix: shift by 1; identity at s == 0; t2 = t3 x t1 ----
    #define EXCL(c1x,c1y,c1z, c3x,c3y,c3z, cpx,cpy,cpz,                         \
                 t1x,t1y,t1z, t2x,t2y,t2z, t3x,t3y,t3z, tpx,tpy,tpz)            \
        float t1x = __shfl_up_sync(0xffffffffu, c1x, 1, 16);                    \
        float t1y = __shfl_up_sync(0xffffffffu, c1y, 1, 16);                    \
        float t1z = __shfl_up_sync(0xffffffffu, c1z, 1, 16);                    \
        float t3x = __shfl_up_sync(0xffffffffu, c3x, 1, 16);                    \
        float t3y = __shfl_up_sync(0xffffffffu, c3y, 1, 16);                    \
        float t3z = __shfl_up_sync(0xffffffffu, c3z, 1, 16);                    \
        float tpx = __shfl_up_sync(0xffffffffu, cpx, 1, 16);                    \
        float tpy = __shfl_up_sync(0xffffffffu, cpy, 1, 16);                    \
        float tpz = __shfl_up_sync(0xffffffffu, cpz, 1, 16);                    \
        if (s == 0) {                                                           \
            t1x = 1.f; t1y = 0.f; t1z = 0.f;                                    \
            t3x = 0.f; t3y = 0.f; t3z = 1.f;                                    \
            tpx = 0.f; tpy = 0.f; tpz = 0.f;                                    \
        }                                                                       \
        float t2x = t3y * t1z - t3z * t1y;                                      \
        float t2y = t3z * t1x - t3x * t1z;                                      \
        float t2z = t3x * t1y - t3y * t1x;

    EXCL(a1x,a1y,a1z, a3x,a3y,a3z, apx,apy,apz,
         u1x,u1y,u1z, u2x,u2y,u2z, u3x,u3y,u3z, upx,upy,upz)
    EXCL(b1x,b1y,b1z, b3x,b3y,b3z, bpx,bpy,bpz,
         v1x,v1y,v1z, v2x,v2y,v2z, v3x,v3y,v3z, vpx,vpy,vpz)
    #undef EXCL

    // ---- phase 3: transform own points for both chains, stage to smem ----
    __syncwarp();
    if (act) {
        float* obA = sw + RECF + (grp * 2 + 0) * 378 + s * 27;
        float* obB = sw + RECF + (grp * 2 + 1) * 378 + s * 27;
        #pragma unroll
        for (int jj = 0; jj < LSEG; ++jj) {
            float qx = qA[jj * 3 + 0];
            float qy = qA[jj * 3 + 1];
            float qz = qA[jj * 3 + 2];
            obA[jj * 3 + 0] = fmaf(qx, u1x, fmaf(qy, u2x, fmaf(qz, u3x, upx)));
            obA[jj * 3 + 1] = fmaf(qx, u1y, fmaf(qy, u2y, fmaf(qz, u3y, upy)));
            obA[jj * 3 + 2] = fmaf(qx, u1z, fmaf(qy, u2z, fmaf(qz, u3z, upz)));
            float rx = qB[jj * 3 + 0];
            float ry = qB[jj * 3 + 1];
            float rz = qB[jj * 3 + 2];
            obB[jj * 3 + 0] = fmaf(rx, v1x, fmaf(ry, v2x, fmaf(rz, v3x, vpx)));
            obB[jj * 3 + 1] = fmaf(rx, v1y, fmaf(ry, v2y, fmaf(rz, v3y, vpy)));
            obB[jj * 3 + 2] = fmaf(rx, v1z, fmaf(ry, v2z, fmaf(rz, v3z, vpz)));
        }
    }
    __syncwarp();

    // ---- phase 4: coalesced float4 flush (1512 floats = 378 float4) ----
    {
        float4*       dst  = (float4*)(out + (size_t)chain0 * (NRES * 3));
        const float4* src4 = (const float4*)(sw + RECF);
        #pragma unroll
        for (int r = 0; r < 12; ++r) {
            int i = lane + r * 32;
            if (i < 378) dst[i] = src4[i];
        }
    }
}

extern "C" void kernel_launch(void* const* d_in, const int* in_sizes, int n_in,
                              void* d_out, int out_size)
{
    const float* angles = (const float*)d_in[0];   // (B, 252) f32
    const float* prev   = (const float*)d_in[1];   // (B, 3, 3) f32
    float*       out    = (float*)d_out;           // (B, 126, 3) f32

    const int B = in_sizes[0] / (2 * NRES);        // 65536
    dihedral_kernel<<<B / (NWARP * 4), TPB>>>(angles, prev, out);
}